// round 3
// baseline (speedup 1.0000x reference)
#include <cuda_runtime.h>
#include <stdint.h>

#define NBINS   29
#define BB      64
#define CC      4
#define QQ      32
#define DD      4096

#define THREADS 256
#define TPC     64          // threads per channel group
#define V4PT    16          // float4 iterations per thread: 4096/(64*4)

__device__ __forceinline__ void proc_elem(float x, int m, uint32_t* histcol) {
    // bit-exact replication of ((x + 1.00001) / 2 * 28).astype(int32):
    // add, *0.5 (exact halving == /2), *28, trunc toward zero.
    float t = __fmul_rn(__fmul_rn(__fadd_rn(x, 1.00001f), 0.5f), 28.0f);
    unsigned bin = (unsigned)__float2int_rz(t);
    bin = min(bin, 28u);                   // memory-safety clamp only
    if (m) histcol[bin * THREADS] += 1u;   // conflict-free: bank = tid % 32
}

__global__ __launch_bounds__(THREADS)
void CountHistogram_kernel(const float* __restrict__ simmat,
                           const int* __restrict__ mask,
                           float* __restrict__ out) {
    __shared__ uint32_t hist[NBINS][THREADS];   // [bin][tid], 29.7 KB

    const int tid = threadIdx.x;
    const int bq  = blockIdx.x;            // 0 .. B*Q-1
    const int b   = bq / QQ;
    const int q   = bq % QQ;

    // zero private histograms
    #pragma unroll
    for (int i = 0; i < NBINS; i++) hist[i][tid] = 0u;
    __syncthreads();

    const int c      = tid >> 6;           // channel group 0..3
    const int lane64 = tid & 63;

    const float4* srow = (const float4*)(simmat +
                          ((((size_t)b * CC + c) * QQ + q) * (size_t)DD));
    const int4*   mrow = (const int4*)(mask +
                          (((size_t)b * QQ + q) * (size_t)DD));

    uint32_t* histcol = &hist[0][tid];

    #pragma unroll 4
    for (int k = 0; k < V4PT; k++) {
        const int v = lane64 + k * TPC;
        float4 s  = srow[v];
        int4   m4 = mrow[v];
        proc_elem(s.x, m4.x, histcol);
        proc_elem(s.y, m4.y, histcol);
        proc_elem(s.z, m4.z, histcol);
        proc_elem(s.w, m4.w, histcol);
    }
    __syncthreads();

    // Reduce 64 per-thread histograms per channel; rotate index by tid so the
    // 32 active lanes hit 32 distinct banks every iteration.
    if (tid < CC * NBINS) {
        const int co  = tid / NBINS;
        const int bin = tid % NBINS;
        uint32_t s = 0u;
        #pragma unroll 8
        for (int j = 0; j < TPC; j++) {
            const int i = (tid + j) & (TPC - 1);
            s += hist[bin][co * TPC + i];
        }
        out[((((size_t)b * CC + co) * QQ + q) * NBINS) + bin] = (float)s;
    }
}

extern "C" void kernel_launch(void* const* d_in, const int* in_sizes, int n_in,
                              void* d_out, int out_size) {
    const float* simmat = (const float*)d_in[0];
    const int*   mask   = (const int*)d_in[1];
    float*       out    = (float*)d_out;
    (void)in_sizes; (void)n_in; (void)out_size;

    dim3 grid(BB * QQ);     // 2048 blocks, one per (b, q)
    dim3 block(THREADS);
    CountHistogram_kernel<<<grid, block>>>(simmat, mask, out);
}

// round 5
// speedup vs baseline: 1.1574x; 1.1574x over previous
#include <cuda_runtime.h>
#include <stdint.h>

#define NBINS   29
#define BB      64
#define CC      4
#define QQ      32
#define DD      4096

#define THREADS 256
#define TPC     64          // threads per channel group
#define V4PT    16          // float4 iterations per thread: 4096/(64*4)

#define HIST_WORDS (NBINS * THREADS)      // u32 words = 29*256 (29.7 KB)

__device__ __forceinline__ void proc_elem(float x, int m, uint8_t* col) {
    // bit-exact: ((x + 1.00001) / 2 * 28) trunc -> int.
    // (x+c)*0.5 is exact (exponent decrement), so ((x+c)*0.5)*28 == (x+c)*14
    // with identical single rounding.
    float t = __fmul_rn(__fadd_rn(x, 1.00001f), 14.0f);
    unsigned bin = (unsigned)__float2int_rz(t);
    bin = min(bin, 28u);                   // memory-safety clamp only
    if (m) col[bin << 10] += (uint8_t)1;   // stride 1024 bytes per bin
}

__global__ __launch_bounds__(THREADS)
void CountHistogram_kernel(const float* __restrict__ simmat,
                           const int* __restrict__ mask,
                           float* __restrict__ out) {
    // 4 independent u8 sub-columns per thread (one per float4 lane).
    // Byte addr = bin*1024 + 4*tid + s  ->  bank = tid % 32, conflict-free,
    // and the 4 streams form independent RMW chains the HW can overlap.
    __shared__ uint32_t histw[HIST_WORDS];
    uint8_t* hist8 = (uint8_t*)histw;

    const int tid = threadIdx.x;
    const int bq  = blockIdx.x;            // 0 .. B*Q-1
    const int b   = bq / QQ;
    const int q   = bq % QQ;

    #pragma unroll
    for (int i = 0; i < NBINS; i++) histw[i * THREADS + tid] = 0u;
    __syncthreads();

    const int c      = tid >> 6;           // channel group 0..3
    const int lane64 = tid & 63;

    const float4* srow = (const float4*)(simmat +
                          ((((size_t)b * CC + c) * QQ + q) * (size_t)DD));
    const int4*   mrow = (const int4*)(mask +
                          (((size_t)b * QQ + q) * (size_t)DD));

    uint8_t* col = hist8 + 4 * tid;        // stream s uses col + s

    #pragma unroll 4
    for (int k = 0; k < V4PT; k++) {
        const int v = lane64 + k * TPC;
        float4 s  = srow[v];
        int4   m4 = mrow[v];
        proc_elem(s.x, m4.x, col + 0);
        proc_elem(s.y, m4.y, col + 1);
        proc_elem(s.z, m4.z, col + 2);
        proc_elem(s.w, m4.w, col + 3);
    }
    __syncthreads();

    // Reduce: output (c, bin) sums 256 bytes = 64 u32 words via dp4a.
    // Word idx = bin*256 + co*64 + j ; rotate j by bin so the 29 active
    // lanes hit distinct banks (bin-stride 256 words == 0 mod 32).
    if (tid < CC * NBINS) {
        const int co  = tid / NBINS;
        const int bin = tid % NBINS;
        const uint32_t* base = histw + bin * THREADS + co * TPC;
        unsigned s = 0u;
        #pragma unroll 8
        for (int i = 0; i < TPC; i++) {
            const int j = (bin + i) & (TPC - 1);
            s = __dp4a(base[j], 0x01010101u, s);
        }
        out[((((size_t)b * CC + co) * QQ + q) * NBINS) + bin] = (float)s;
    }
}

extern "C" void kernel_launch(void* const* d_in, const int* in_sizes, int n_in,
                              void* d_out, int out_size) {
    const float* simmat = (const float*)d_in[0];
    const int*   mask   = (const int*)d_in[1];
    float*       out    = (float*)d_out;
    (void)in_sizes; (void)n_in; (void)out_size;

    dim3 grid(BB * QQ);     // 2048 blocks, one per (b, q)
    dim3 block(THREADS);
    CountHistogram_kernel<<<grid, block>>>(simmat, mask, out);
}